// round 4
// baseline (speedup 1.0000x reference)
#include <cuda_runtime.h>
#include <cstdint>

#define N_NODES 50000
#define N_EDGES 800000
#define D 256

// ---------------- scratch (device globals; no allocations) ----------------
__device__ int   g_is64;
__device__ int   g_esrc[N_EDGES];
__device__ int   g_edst[N_EDGES];
__device__ int   g_deg[N_NODES];
__device__ int   g_rowptr[N_NODES + 1];
__device__ int   g_cursor[N_NODES];
__device__ int   g_srcs[N_EDGES];
__device__ float g_bufA[N_NODES * D];   // agg scratch, later A_pre
__device__ float g_bufB[N_NODES * D];   // h1, later B_pre
__device__ float g_bufC[N_NODES * D];   // h2

// selector: 0 -> g_bufA, 1 -> g_bufB, 2 -> g_bufC, else nullptr
__device__ __forceinline__ float* selbuf(int s) {
    if (s == 0) return g_bufA;
    if (s == 1) return g_bufB;
    if (s == 2) return g_bufC;
    return nullptr;
}

// ---------------- edge index ingestion (dtype-robust) ----------------
// If the harness delivers int64 edge_index, every odd 32-bit word of the
// first half is a zero hi-word (node ids < 50000). If int32, those words are
// random node ids. Decide on device; no host readback (graph-capturable).
__global__ void detect_kernel(const int* __restrict__ ei32) {
    if (threadIdx.x == 0 && blockIdx.x == 0) {
        int allzero = 1;
        for (int i = 1; i < 256; i += 2) {
            if (ei32[i] != 0) { allzero = 0; break; }
        }
        g_is64 = allzero;
    }
}

__global__ void convert_kernel(const void* __restrict__ ei) {
    int e = blockIdx.x * blockDim.x + threadIdx.x;
    if (e >= N_EDGES) return;
    if (g_is64) {
        const long long* p = (const long long*)ei;
        g_esrc[e] = (int)p[e];
        g_edst[e] = (int)p[N_EDGES + e];
    } else {
        const int* p = (const int*)ei;
        g_esrc[e] = p[e];
        g_edst[e] = p[N_EDGES + e];
    }
}

// ---------------- CSR build ----------------
__global__ void zero_deg_kernel() {
    int i = blockIdx.x * blockDim.x + threadIdx.x;
    if (i < N_NODES) g_deg[i] = 0;
}

__global__ void count_kernel() {
    int e = blockIdx.x * blockDim.x + threadIdx.x;
    if (e < N_EDGES) {
        atomicAdd(&g_deg[g_edst[e]], 1);
    }
}

__global__ void scan_kernel() {
    __shared__ int sh[1024];
    const int CH = 49;  // 1024*49 = 50176 >= 50000
    int t = threadIdx.x;
    int base = t * CH;
    int s = 0;
    for (int i = 0; i < CH; i++) {
        int idx = base + i;
        if (idx < N_NODES) s += g_deg[idx];
    }
    sh[t] = s;
    __syncthreads();
    // Hillis-Steele inclusive scan
    for (int o = 1; o < 1024; o <<= 1) {
        int v = (t >= o) ? sh[t - o] : 0;
        __syncthreads();
        sh[t] += v;
        __syncthreads();
    }
    int run = sh[t] - s;  // exclusive prefix
    for (int i = 0; i < CH; i++) {
        int idx = base + i;
        if (idx < N_NODES) {
            g_rowptr[idx] = run;
            g_cursor[idx] = run;
            run += g_deg[idx];
        }
    }
    if (t == 0) g_rowptr[N_NODES] = N_EDGES;
}

__global__ void fill_kernel() {
    int e = blockIdx.x * blockDim.x + threadIdx.x;
    if (e < N_EDGES) {
        int pos = atomicAdd(&g_cursor[g_edst[e]], 1);
        g_srcs[pos] = g_esrc[e];
    }
}

// ---------------- mean aggregation: one warp per node ----------------
__global__ void aggregate_kernel(const float* __restrict__ in_ext, int in_sel, int out_sel) {
    const float* in = in_ext ? in_ext : selbuf(in_sel);
    float* out = selbuf(out_sel);
    int gtid = blockIdx.x * blockDim.x + threadIdx.x;
    int node = gtid >> 5;
    int lane = gtid & 31;
    if (node >= N_NODES) return;
    int beg = g_rowptr[node], end = g_rowptr[node + 1];
    float4 acc0 = make_float4(0.f, 0.f, 0.f, 0.f);
    float4 acc1 = make_float4(0.f, 0.f, 0.f, 0.f);
    for (int p = beg; p < end; p++) {
        int s = g_srcs[p];
        const float4* ps = (const float4*)(in + (size_t)s * D);
        float4 a = ps[lane];
        float4 b = ps[lane + 32];
        acc0.x += a.x; acc0.y += a.y; acc0.z += a.z; acc0.w += a.w;
        acc1.x += b.x; acc1.y += b.y; acc1.z += b.z; acc1.w += b.w;
    }
    float inv = 1.f / fmaxf((float)(end - beg), 1.f);
    acc0.x *= inv; acc0.y *= inv; acc0.z *= inv; acc0.w *= inv;
    acc1.x *= inv; acc1.y *= inv; acc1.z *= inv; acc1.w *= inv;
    float4* po = (float4*)(out + (size_t)node * D);
    po[lane] = acc0;
    po[lane + 32] = acc1;
}

// ---------------- fp32 SGEMM: C[M,256] = act(A1@W1 (+ A2@W2) (+ bias)) ----------------
#define BM 128
#define BN 128
#define BK 16

template <bool DUAL, bool RELU, bool BIAS>
__global__ void gemm_kernel(const float* __restrict__ A1ext, int a1_sel,
                            const float* __restrict__ W1,
                            const float* __restrict__ A2ext, int a2_sel,
                            const float* __restrict__ W2,
                            const float* __restrict__ bias, int c_sel) {
    __shared__ float As[BK][BM + 4];
    __shared__ float Ws[BK][BN];

    const float* A1 = A1ext ? A1ext : selbuf(a1_sel);
    const float* A2 = DUAL ? (A2ext ? A2ext : selbuf(a2_sel)) : nullptr;
    float* C = selbuf(c_sel);

    int tid = threadIdx.x;
    int tx = tid & 15;      // 0..15 -> column groups
    int ty = tid >> 4;      // 0..15 -> row groups
    int m0 = blockIdx.y * BM;
    int n0 = blockIdx.x * BN;

    float acc[8][8];
#pragma unroll
    for (int i = 0; i < 8; i++)
#pragma unroll
        for (int j = 0; j < 8; j++) acc[i][j] = 0.f;

    int nPass = DUAL ? 2 : 1;
#pragma unroll 1
    for (int pass = 0; pass < nPass; pass++) {
        const float* A = (DUAL && pass) ? A2 : A1;
        const float* W = (DUAL && pass) ? W2 : W1;
#pragma unroll 1
        for (int k0 = 0; k0 < 256; k0 += BK) {
            // load A tile (128 rows x 16 k), transposed into As[k][m]
#pragma unroll
            for (int i = 0; i < 2; i++) {
                int row = (tid >> 2) + i * 64;
                int col4 = tid & 3;
                int gm = m0 + row;
                float4 v = make_float4(0.f, 0.f, 0.f, 0.f);
                if (gm < N_NODES)
                    v = *(const float4*)(A + (size_t)gm * 256 + k0 + col4 * 4);
                As[col4 * 4 + 0][row] = v.x;
                As[col4 * 4 + 1][row] = v.y;
                As[col4 * 4 + 2][row] = v.z;
                As[col4 * 4 + 3][row] = v.w;
            }
            // load W tile (16 k x 128 n)
#pragma unroll
            for (int i = 0; i < 2; i++) {
                int kr = (tid >> 5) + i * 8;
                int c4 = tid & 31;
                *(float4*)&Ws[kr][c4 * 4] =
                    *(const float4*)(W + (size_t)(k0 + kr) * 256 + n0 + c4 * 4);
            }
            __syncthreads();
#pragma unroll
            for (int k = 0; k < BK; k++) {
                float a[8], b[8];
                *(float4*)(a)     = *(float4*)&As[k][ty * 4];
                *(float4*)(a + 4) = *(float4*)&As[k][64 + ty * 4];
                *(float4*)(b)     = *(float4*)&Ws[k][tx * 4];
                *(float4*)(b + 4) = *(float4*)&Ws[k][64 + tx * 4];
#pragma unroll
                for (int i = 0; i < 8; i++)
#pragma unroll
                    for (int j = 0; j < 8; j++)
                        acc[i][j] = fmaf(a[i], b[j], acc[i][j]);
            }
            __syncthreads();
        }
    }

    // epilogue
    float4 bias0 = make_float4(0.f, 0.f, 0.f, 0.f);
    float4 bias1 = make_float4(0.f, 0.f, 0.f, 0.f);
    if (BIAS) {
        bias0 = *(const float4*)(bias + n0 + tx * 4);
        bias1 = *(const float4*)(bias + n0 + 64 + tx * 4);
    }
#pragma unroll
    for (int i = 0; i < 8; i++) {
        int gm = m0 + ty * 4 + (i & 3) + (i >> 2) * 64;
        if (gm >= N_NODES) continue;
        float* crow = C + (size_t)gm * 256 + n0;
        float4 v0, v1;
        v0.x = acc[i][0] + bias0.x; v0.y = acc[i][1] + bias0.y;
        v0.z = acc[i][2] + bias0.z; v0.w = acc[i][3] + bias0.w;
        v1.x = acc[i][4] + bias1.x; v1.y = acc[i][5] + bias1.y;
        v1.z = acc[i][6] + bias1.z; v1.w = acc[i][7] + bias1.w;
        if (RELU) {
            v0.x = fmaxf(v0.x, 0.f); v0.y = fmaxf(v0.y, 0.f);
            v0.z = fmaxf(v0.z, 0.f); v0.w = fmaxf(v0.w, 0.f);
            v1.x = fmaxf(v1.x, 0.f); v1.y = fmaxf(v1.y, 0.f);
            v1.z = fmaxf(v1.z, 0.f); v1.w = fmaxf(v1.w, 0.f);
        }
        *(float4*)(crow + tx * 4) = v0;
        *(float4*)(crow + 64 + tx * 4) = v1;
    }
}

// ---------------- edge MLP: one warp per edge ----------------
// out[e] = relu(A[src] + B[dst]) @ Wm2 + bm2   (bm1 already folded into B)
__global__ void edge_kernel(const float* __restrict__ Wm2,
                            const float* __restrict__ bm2,
                            float* __restrict__ out) {
    __shared__ __align__(16) float w0[256];
    __shared__ __align__(16) float w1[256];
    for (int i = threadIdx.x; i < 256; i += blockDim.x) {
        w0[i] = Wm2[i * 2 + 0];
        w1[i] = Wm2[i * 2 + 1];
    }
    __syncthreads();

    int gtid = blockIdx.x * blockDim.x + threadIdx.x;
    int e = gtid >> 5;
    int lane = gtid & 31;
    if (e >= N_EDGES) return;

    int s = g_esrc[e];
    int d = g_edst[e];
    const float4* pa = (const float4*)(g_bufA + (size_t)s * D);
    const float4* pb = (const float4*)(g_bufB + (size_t)d * D);
    const float4* w0f = (const float4*)w0;
    const float4* w1f = (const float4*)w1;

    float acc0 = 0.f, acc1 = 0.f;
#pragma unroll
    for (int i = 0; i < 2; i++) {
        int idx = lane + i * 32;
        float4 a = pa[idx];
        float4 b = pb[idx];
        float4 v;
        v.x = fmaxf(a.x + b.x, 0.f);
        v.y = fmaxf(a.y + b.y, 0.f);
        v.z = fmaxf(a.z + b.z, 0.f);
        v.w = fmaxf(a.w + b.w, 0.f);
        float4 wa = w0f[idx];
        float4 wb = w1f[idx];
        acc0 = fmaf(v.x, wa.x, acc0); acc0 = fmaf(v.y, wa.y, acc0);
        acc0 = fmaf(v.z, wa.z, acc0); acc0 = fmaf(v.w, wa.w, acc0);
        acc1 = fmaf(v.x, wb.x, acc1); acc1 = fmaf(v.y, wb.y, acc1);
        acc1 = fmaf(v.z, wb.z, acc1); acc1 = fmaf(v.w, wb.w, acc1);
    }
#pragma unroll
    for (int o = 16; o > 0; o >>= 1) {
        acc0 += __shfl_xor_sync(0xFFFFFFFFu, acc0, o);
        acc1 += __shfl_xor_sync(0xFFFFFFFFu, acc1, o);
    }
    if (lane == 0) {
        float2 r;
        r.x = acc0 + bm2[0];
        r.y = acc1 + bm2[1];
        *(float2*)(out + (size_t)e * 2) = r;
    }
}

// ---------------- launch ----------------
extern "C" void kernel_launch(void* const* d_in, const int* in_sizes, int n_in,
                              void* d_out, int out_size) {
    const float* x   = (const float*)d_in[0];
    const void*  ei  = d_in[1];
    const float* W1l = (const float*)d_in[2];
    const float* b1l = (const float*)d_in[3];
    const float* W1r = (const float*)d_in[4];
    const float* W2l = (const float*)d_in[5];
    const float* b2l = (const float*)d_in[6];
    const float* W2r = (const float*)d_in[7];
    const float* Wm1 = (const float*)d_in[8];
    const float* bm1 = (const float*)d_in[9];
    const float* Wm2 = (const float*)d_in[10];
    const float* bm2 = (const float*)d_in[11];
    float* out = (float*)d_out;

    // edge-index ingestion (robust to int32 vs int64 delivery)
    detect_kernel<<<1, 32>>>((const int*)ei);
    convert_kernel<<<(N_EDGES + 255) / 256, 256>>>(ei);

    // CSR build
    zero_deg_kernel<<<(N_NODES + 255) / 256, 256>>>();
    count_kernel<<<(N_EDGES + 255) / 256, 256>>>();
    scan_kernel<<<1, 1024>>>();
    fill_kernel<<<(N_EDGES + 255) / 256, 256>>>();

    dim3 ggrid(2, (N_NODES + BM - 1) / BM);
    int aggBlocks = (N_NODES * 32 + 255) / 256;
    int edgeBlocks = (N_EDGES * 32 + 255) / 256;

    // layer 1: agg(x) -> bufA(0) ; h1 = relu(agg@W1l + x@W1r + b1l) -> bufB(1)
    aggregate_kernel<<<aggBlocks, 256>>>(x, -1, 0);
    gemm_kernel<true, true, true><<<ggrid, 256>>>(nullptr, 0, W1l, x, -1, W1r, b1l, 1);

    // layer 2: agg(h1) -> bufA(0) ; h2 = relu(agg@W2l + h1@W2r + b2l) -> bufC(2)
    aggregate_kernel<<<aggBlocks, 256>>>(nullptr, 1, 0);
    gemm_kernel<true, true, true><<<ggrid, 256>>>(nullptr, 0, W2l, nullptr, 1, W2r, b2l, 2);

    // edge precompute: A_pre = h2 @ Wm1_top -> bufA(0) ; B_pre = h2 @ Wm1_bot + bm1 -> bufB(1)
    gemm_kernel<false, false, false><<<ggrid, 256>>>(nullptr, 2, Wm1, nullptr, -1, nullptr, nullptr, 0);
    gemm_kernel<false, false, true><<<ggrid, 256>>>(nullptr, 2, Wm1 + 256 * 256, nullptr, -1, nullptr, bm1, 1);

    // edge MLP
    edge_kernel<<<edgeBlocks, 256>>>(Wm2, bm2, out);
}

// round 5
// speedup vs baseline: 1.5136x; 1.5136x over previous
#include <cuda_runtime.h>
#include <cstdint>

#define N_NODES 50000
#define N_EDGES 800000
#define D 256

// ---------------- scratch (device globals; no allocations) ----------------
__device__ int   g_is64;
__device__ int   g_esrc[N_EDGES];
__device__ int   g_edst[N_EDGES];
__device__ int   g_deg[N_NODES];
__device__ int   g_rowptr[N_NODES + 1];
__device__ int   g_cursor[N_NODES];
__device__ int   g_srcs[N_EDGES];
__device__ float g_bufA[N_NODES * D];   // agg scratch, later A_pre
__device__ float g_bufB[N_NODES * D];   // h1, later B_pre
__device__ float g_bufC[N_NODES * D];   // h2

// selector: 0 -> g_bufA, 1 -> g_bufB, 2 -> g_bufC, else nullptr
__device__ __forceinline__ float* selbuf(int s) {
    if (s == 0) return g_bufA;
    if (s == 1) return g_bufB;
    if (s == 2) return g_bufC;
    return nullptr;
}

// ---------------- edge index ingestion (dtype-robust) ----------------
__global__ void detect_kernel(const int* __restrict__ ei32) {
    if (threadIdx.x == 0 && blockIdx.x == 0) {
        int allzero = 1;
        for (int i = 1; i < 256; i += 2) {
            if (ei32[i] != 0) { allzero = 0; break; }
        }
        g_is64 = allzero;
    }
}

__global__ void convert_kernel(const void* __restrict__ ei) {
    int e = blockIdx.x * blockDim.x + threadIdx.x;
    if (e >= N_EDGES) return;
    if (g_is64) {
        const long long* p = (const long long*)ei;
        g_esrc[e] = (int)p[e];
        g_edst[e] = (int)p[N_EDGES + e];
    } else {
        const int* p = (const int*)ei;
        g_esrc[e] = p[e];
        g_edst[e] = p[N_EDGES + e];
    }
}

// ---------------- CSR build ----------------
__global__ void zero_deg_kernel() {
    int i = blockIdx.x * blockDim.x + threadIdx.x;
    if (i < N_NODES) g_deg[i] = 0;
}

__global__ void count_kernel() {
    int e = blockIdx.x * blockDim.x + threadIdx.x;
    if (e < N_EDGES) {
        atomicAdd(&g_deg[g_edst[e]], 1);
    }
}

__global__ void scan_kernel() {
    __shared__ int sh[1024];
    const int CH = 49;
    int t = threadIdx.x;
    int base = t * CH;
    int s = 0;
    for (int i = 0; i < CH; i++) {
        int idx = base + i;
        if (idx < N_NODES) s += g_deg[idx];
    }
    sh[t] = s;
    __syncthreads();
    for (int o = 1; o < 1024; o <<= 1) {
        int v = (t >= o) ? sh[t - o] : 0;
        __syncthreads();
        sh[t] += v;
        __syncthreads();
    }
    int run = sh[t] - s;
    for (int i = 0; i < CH; i++) {
        int idx = base + i;
        if (idx < N_NODES) {
            g_rowptr[idx] = run;
            g_cursor[idx] = run;
            run += g_deg[idx];
        }
    }
    if (t == 0) g_rowptr[N_NODES] = N_EDGES;
}

__global__ void fill_kernel() {
    int e = blockIdx.x * blockDim.x + threadIdx.x;
    if (e < N_EDGES) {
        int pos = atomicAdd(&g_cursor[g_edst[e]], 1);
        g_srcs[pos] = g_esrc[e];
    }
}

// ---------------- mean aggregation: one warp per node ----------------
__global__ void aggregate_kernel(const float* __restrict__ in_ext, int in_sel, int out_sel) {
    const float* in = in_ext ? in_ext : selbuf(in_sel);
    float* out = selbuf(out_sel);
    int gtid = blockIdx.x * blockDim.x + threadIdx.x;
    int node = gtid >> 5;
    int lane = gtid & 31;
    if (node >= N_NODES) return;
    int beg = g_rowptr[node], end = g_rowptr[node + 1];
    float4 acc0 = make_float4(0.f, 0.f, 0.f, 0.f);
    float4 acc1 = make_float4(0.f, 0.f, 0.f, 0.f);
    for (int p = beg; p < end; p++) {
        int s = g_srcs[p];
        const float4* ps = (const float4*)(in + (size_t)s * D);
        float4 a = ps[lane];
        float4 b = ps[lane + 32];
        acc0.x += a.x; acc0.y += a.y; acc0.z += a.z; acc0.w += a.w;
        acc1.x += b.x; acc1.y += b.y; acc1.z += b.z; acc1.w += b.w;
    }
    float inv = 1.f / fmaxf((float)(end - beg), 1.f);
    acc0.x *= inv; acc0.y *= inv; acc0.z *= inv; acc0.w *= inv;
    acc1.x *= inv; acc1.y *= inv; acc1.z *= inv; acc1.w *= inv;
    float4* po = (float4*)(out + (size_t)node * D);
    po[lane] = acc0;
    po[lane + 32] = acc1;
}

// ---------------- tf32 tensor-core GEMM ----------------
// C[M,256] = act(A1@W1 (+ A2@W2) (+ bias)), K = 256, all row-major, stride 256.
// 128x128 block tile, BK=16 double-buffered, 8 warps of 32x64 (2x8 m16n8k8).
#define BM 128
#define BN 128
#define BK 16

__device__ __forceinline__ uint32_t f2tf32(float f) {
    uint32_t r;
    asm("cvt.rna.tf32.f32 %0, %1;" : "=r"(r) : "f"(f));
    return r;
}

__device__ __forceinline__ void mma_tf32(float* c, uint32_t a0, uint32_t a1,
                                         uint32_t a2, uint32_t a3,
                                         uint32_t b0, uint32_t b1) {
    asm volatile(
        "mma.sync.aligned.m16n8k8.row.col.f32.tf32.tf32.f32 "
        "{%0,%1,%2,%3}, {%4,%5,%6,%7}, {%8,%9}, {%0,%1,%2,%3};"
        : "+f"(c[0]), "+f"(c[1]), "+f"(c[2]), "+f"(c[3])
        : "r"(a0), "r"(a1), "r"(a2), "r"(a3), "r"(b0), "r"(b1));
}

template <bool DUAL, bool RELU, bool BIAS>
__global__ __launch_bounds__(256, 1)
void gemm_kernel(const float* __restrict__ A1ext, int a1_sel,
                 const float* __restrict__ W1,
                 const float* __restrict__ A2ext, int a2_sel,
                 const float* __restrict__ W2,
                 const float* __restrict__ bias, int c_sel) {
    __shared__ float As[2][BM][BK + 4];    // stride 20: conflict-free frag reads
    __shared__ float Ws[2][BK][BN + 8];    // stride 136: conflict-free frag reads

    const float* A1 = A1ext ? A1ext : selbuf(a1_sel);
    const float* A2 = DUAL ? (A2ext ? A2ext : selbuf(a2_sel)) : nullptr;
    float* C = selbuf(c_sel);

    const int tid = threadIdx.x;
    const int lane = tid & 31;
    const int warp = tid >> 5;
    const int wm = warp & 3;          // 4 warps along M
    const int wn = warp >> 2;         // 2 warps along N
    const int m0 = blockIdx.y * BM;
    const int n0 = blockIdx.x * BN;

    const int itersPerPass = 256 / BK;            // 16
    const int total = DUAL ? 2 * itersPerPass : itersPerPass;

    float acc[2][8][4];
#pragma unroll
    for (int i = 0; i < 2; i++)
#pragma unroll
        for (int j = 0; j < 8; j++)
#pragma unroll
            for (int r = 0; r < 4; r++) acc[i][j][r] = 0.f;

    // per-thread load coordinates
    // A tile: 128 rows x 16 k = 512 float4; thread does j = tid, tid+256
    const int ar0 = tid >> 2, ac0 = (tid & 3) * 4;           // j = tid
    const int ar1 = (tid + 256) >> 2;                        // j = tid+256 (same ac)
    // W tile: 16 k x 128 n = 512 float4
    const int wk0 = tid >> 5, wc0 = (tid & 31) * 4;
    const int wk1 = (tid + 256) >> 5;

    auto loadA = [&](const float* A, int kk, float4& v0, float4& v1) {
        int gm0 = m0 + ar0, gm1 = m0 + ar1;
        v0 = (gm0 < N_NODES) ? *(const float4*)(A + (size_t)gm0 * 256 + kk + ac0)
                             : make_float4(0.f, 0.f, 0.f, 0.f);
        v1 = (gm1 < N_NODES) ? *(const float4*)(A + (size_t)gm1 * 256 + kk + ac0)
                             : make_float4(0.f, 0.f, 0.f, 0.f);
    };
    auto loadW = [&](const float* W, int kk, float4& v0, float4& v1) {
        v0 = *(const float4*)(W + (size_t)(kk + wk0) * 256 + n0 + wc0);
        v1 = *(const float4*)(W + (size_t)(kk + wk1) * 256 + n0 + wc0);
    };
    auto storeTile = [&](int buf, const float4& a0v, const float4& a1v,
                         const float4& w0v, const float4& w1v) {
        *(float4*)&As[buf][ar0][ac0] = a0v;
        *(float4*)&As[buf][ar1][ac0] = a1v;
        *(float4*)&Ws[buf][wk0][wc0] = w0v;
        *(float4*)&Ws[buf][wk1][wc0] = w1v;
    };

    // prologue: iter 0 into buffer 0
    {
        float4 a0v, a1v, w0v, w1v;
        loadA(A1, 0, a0v, a1v);
        loadW(W1, 0, w0v, w1v);
        storeTile(0, a0v, a1v, w0v, w1v);
    }
    __syncthreads();

    const int mbase = wm * 32;
    const int nbase = wn * 64;
    const int fr = lane >> 2;      // fragment row
    const int fc = lane & 3;       // fragment col/k

    for (int it = 0; it < total; it++) {
        int buf = it & 1;
        float4 pa0, pa1, pw0, pw1;
        bool more = (it + 1) < total;
        if (more) {
            int nit = it + 1;
            const float* A = (DUAL && nit >= itersPerPass) ? A2 : A1;
            const float* W = (DUAL && nit >= itersPerPass) ? W2 : W1;
            int kk = (nit & (itersPerPass - 1)) * BK;
            loadA(A, kk, pa0, pa1);
            loadW(W, kk, pw0, pw1);
        }

#pragma unroll
        for (int ks = 0; ks < 2; ks++) {
            int kk = ks * 8;
            uint32_t af[2][4];
#pragma unroll
            for (int mt = 0; mt < 2; mt++) {
                int r = mbase + mt * 16 + fr;
                af[mt][0] = f2tf32(As[buf][r][kk + fc]);
                af[mt][1] = f2tf32(As[buf][r + 8][kk + fc]);
                af[mt][2] = f2tf32(As[buf][r][kk + fc + 4]);
                af[mt][3] = f2tf32(As[buf][r + 8][kk + fc + 4]);
            }
            uint32_t bf[8][2];
#pragma unroll
            for (int nt = 0; nt < 8; nt++) {
                int n = nbase + nt * 8 + fr;
                bf[nt][0] = f2tf32(Ws[buf][kk + fc][n]);
                bf[nt][1] = f2tf32(Ws[buf][kk + fc + 4][n]);
            }
#pragma unroll
            for (int mt = 0; mt < 2; mt++)
#pragma unroll
                for (int nt = 0; nt < 8; nt++)
                    mma_tf32(acc[mt][nt], af[mt][0], af[mt][1], af[mt][2], af[mt][3],
                             bf[nt][0], bf[nt][1]);
        }

        if (more) storeTile(buf ^ 1, pa0, pa1, pw0, pw1);
        __syncthreads();
    }

    // epilogue: c0/c1 at (fr, 2*fc), c2/c3 at (fr+8, 2*fc)
#pragma unroll
    for (int mt = 0; mt < 2; mt++) {
#pragma unroll
        for (int nt = 0; nt < 8; nt++) {
            int gn = n0 + nbase + nt * 8 + 2 * fc;
            float b0 = BIAS ? bias[gn] : 0.f;
            float b1 = BIAS ? bias[gn + 1] : 0.f;
            int gm0 = m0 + mbase + mt * 16 + fr;
            int gm1 = gm0 + 8;
            float2 v0, v1;
            v0.x = acc[mt][nt][0] + b0; v0.y = acc[mt][nt][1] + b1;
            v1.x = acc[mt][nt][2] + b0; v1.y = acc[mt][nt][3] + b1;
            if (RELU) {
                v0.x = fmaxf(v0.x, 0.f); v0.y = fmaxf(v0.y, 0.f);
                v1.x = fmaxf(v1.x, 0.f); v1.y = fmaxf(v1.y, 0.f);
            }
            if (gm0 < N_NODES) *(float2*)(C + (size_t)gm0 * 256 + gn) = v0;
            if (gm1 < N_NODES) *(float2*)(C + (size_t)gm1 * 256 + gn) = v1;
        }
    }
}

// ---------------- edge MLP: one warp per edge ----------------
__global__ void edge_kernel(const float* __restrict__ Wm2,
                            const float* __restrict__ bm2,
                            float* __restrict__ out) {
    __shared__ __align__(16) float w0[256];
    __shared__ __align__(16) float w1[256];
    for (int i = threadIdx.x; i < 256; i += blockDim.x) {
        w0[i] = Wm2[i * 2 + 0];
        w1[i] = Wm2[i * 2 + 1];
    }
    __syncthreads();

    int gtid = blockIdx.x * blockDim.x + threadIdx.x;
    int e = gtid >> 5;
    int lane = gtid & 31;
    if (e >= N_EDGES) return;

    int s = g_esrc[e];
    int d = g_edst[e];
    const float4* pa = (const float4*)(g_bufA + (size_t)s * D);
    const float4* pb = (const float4*)(g_bufB + (size_t)d * D);
    const float4* w0f = (const float4*)w0;
    const float4* w1f = (const float4*)w1;

    float acc0 = 0.f, acc1 = 0.f;
#pragma unroll
    for (int i = 0; i < 2; i++) {
        int idx = lane + i * 32;
        float4 a = pa[idx];
        float4 b = pb[idx];
        float4 v;
        v.x = fmaxf(a.x + b.x, 0.f);
        v.y = fmaxf(a.y + b.y, 0.f);
        v.z = fmaxf(a.z + b.z, 0.f);
        v.w = fmaxf(a.w + b.w, 0.f);
        float4 wa = w0f[idx];
        float4 wb = w1f[idx];
        acc0 = fmaf(v.x, wa.x, acc0); acc0 = fmaf(v.y, wa.y, acc0);
        acc0 = fmaf(v.z, wa.z, acc0); acc0 = fmaf(v.w, wa.w, acc0);
        acc1 = fmaf(v.x, wb.x, acc1); acc1 = fmaf(v.y, wb.y, acc1);
        acc1 = fmaf(v.z, wb.z, acc1); acc1 = fmaf(v.w, wb.w, acc1);
    }
#pragma unroll
    for (int o = 16; o > 0; o >>= 1) {
        acc0 += __shfl_xor_sync(0xFFFFFFFFu, acc0, o);
        acc1 += __shfl_xor_sync(0xFFFFFFFFu, acc1, o);
    }
    if (lane == 0) {
        float2 r;
        r.x = acc0 + bm2[0];
        r.y = acc1 + bm2[1];
        *(float2*)(out + (size_t)e * 2) = r;
    }
}

// ---------------- launch ----------------
extern "C" void kernel_launch(void* const* d_in, const int* in_sizes, int n_in,
                              void* d_out, int out_size) {
    const float* x   = (const float*)d_in[0];
    const void*  ei  = d_in[1];
    const float* W1l = (const float*)d_in[2];
    const float* b1l = (const float*)d_in[3];
    const float* W1r = (const float*)d_in[4];
    const float* W2l = (const float*)d_in[5];
    const float* b2l = (const float*)d_in[6];
    const float* W2r = (const float*)d_in[7];
    const float* Wm1 = (const float*)d_in[8];
    const float* bm1 = (const float*)d_in[9];
    const float* Wm2 = (const float*)d_in[10];
    const float* bm2 = (const float*)d_in[11];
    float* out = (float*)d_out;

    // edge-index ingestion (robust to int32 vs int64 delivery)
    detect_kernel<<<1, 32>>>((const int*)ei);
    convert_kernel<<<(N_EDGES + 255) / 256, 256>>>(ei);

    // CSR build
    zero_deg_kernel<<<(N_NODES + 255) / 256, 256>>>();
    count_kernel<<<(N_EDGES + 255) / 256, 256>>>();
    scan_kernel<<<1, 1024>>>();
    fill_kernel<<<(N_EDGES + 255) / 256, 256>>>();

    dim3 ggrid(2, (N_NODES + BM - 1) / BM);
    int aggBlocks = (N_NODES * 32 + 255) / 256;
    int edgeBlocks = (N_EDGES * 32 + 255) / 256;

    // layer 1: agg(x) -> bufA(0) ; h1 = relu(agg@W1l + x@W1r + b1l) -> bufB(1)
    aggregate_kernel<<<aggBlocks, 256>>>(x, -1, 0);
    gemm_kernel<true, true, true><<<ggrid, 256>>>(nullptr, 0, W1l, x, -1, W1r, b1l, 1);

    // layer 2: agg(h1) -> bufA(0) ; h2 = relu(agg@W2l + h1@W2r + b2l) -> bufC(2)
    aggregate_kernel<<<aggBlocks, 256>>>(nullptr, 1, 0);
    gemm_kernel<true, true, true><<<ggrid, 256>>>(nullptr, 0, W2l, nullptr, 1, W2r, b2l, 2);

    // edge precompute: A_pre = h2 @ Wm1_top -> bufA(0) ; B_pre = h2 @ Wm1_bot + bm1 -> bufB(1)
    gemm_kernel<false, false, false><<<ggrid, 256>>>(nullptr, 2, Wm1, nullptr, -1, nullptr, nullptr, 0);
    gemm_kernel<false, false, true><<<ggrid, 256>>>(nullptr, 2, Wm1 + 256 * 256, nullptr, -1, nullptr, bm1, 1);

    // edge MLP
    edge_kernel<<<edgeBlocks, 256>>>(Wm2, bm2, out);
}

// round 8
// speedup vs baseline: 1.7135x; 1.1321x over previous
#include <cuda_runtime.h>
#include <cstdint>

#define N_NODES 50000
#define N_EDGES 800000
#define D 256

// ---------------- scratch (device globals; no allocations) ----------------
__device__ int   g_is64;
__device__ int   g_esrc[N_EDGES];
__device__ int   g_edst[N_EDGES];
__device__ int   g_deg[N_NODES];
__device__ int   g_rowptr[N_NODES + 1];
__device__ int   g_cursor[N_NODES];
__device__ int   g_srcs[N_EDGES];
__device__ float g_bufA[N_NODES * D];   // agg scratch, later A_pre
__device__ float g_bufB[N_NODES * D];   // h1, later B_pre
__device__ float g_bufC[N_NODES * D];   // h2

// selector: 0 -> g_bufA, 1 -> g_bufB, 2 -> g_bufC, else nullptr
__device__ __forceinline__ float* selbuf(int s) {
    if (s == 0) return g_bufA;
    if (s == 1) return g_bufB;
    if (s == 2) return g_bufC;
    return nullptr;
}

// ---------------- edge index ingestion (dtype-robust) ----------------
__global__ void detect_kernel(const int* __restrict__ ei32) {
    if (threadIdx.x == 0 && blockIdx.x == 0) {
        int allzero = 1;
        for (int i = 1; i < 256; i += 2) {
            if (ei32[i] != 0) { allzero = 0; break; }
        }
        g_is64 = allzero;
    }
}

__global__ void convert_kernel(const void* __restrict__ ei) {
    int e = blockIdx.x * blockDim.x + threadIdx.x;
    if (e >= N_EDGES) return;
    if (g_is64) {
        const long long* p = (const long long*)ei;
        g_esrc[e] = (int)p[e];
        g_edst[e] = (int)p[N_EDGES + e];
    } else {
        const int* p = (const int*)ei;
        g_esrc[e] = p[e];
        g_edst[e] = p[N_EDGES + e];
    }
}

// ---------------- CSR build ----------------
__global__ void zero_deg_kernel() {
    int i = blockIdx.x * blockDim.x + threadIdx.x;
    if (i < N_NODES) g_deg[i] = 0;
}

__global__ void count_kernel() {
    int e = blockIdx.x * blockDim.x + threadIdx.x;
    if (e < N_EDGES) {
        atomicAdd(&g_deg[g_edst[e]], 1);
    }
}

__global__ void scan_kernel() {
    __shared__ int sh[1024];
    const int CH = 49;
    int t = threadIdx.x;
    int base = t * CH;
    int s = 0;
    for (int i = 0; i < CH; i++) {
        int idx = base + i;
        if (idx < N_NODES) s += g_deg[idx];
    }
    sh[t] = s;
    __syncthreads();
    for (int o = 1; o < 1024; o <<= 1) {
        int v = (t >= o) ? sh[t - o] : 0;
        __syncthreads();
        sh[t] += v;
        __syncthreads();
    }
    int run = sh[t] - s;
    for (int i = 0; i < CH; i++) {
        int idx = base + i;
        if (idx < N_NODES) {
            g_rowptr[idx] = run;
            g_cursor[idx] = run;
            run += g_deg[idx];
        }
    }
    if (t == 0) g_rowptr[N_NODES] = N_EDGES;
}

__global__ void fill_kernel() {
    int e = blockIdx.x * blockDim.x + threadIdx.x;
    if (e < N_EDGES) {
        int pos = atomicAdd(&g_cursor[g_edst[e]], 1);
        g_srcs[pos] = g_esrc[e];
    }
}

// ---------------- mean aggregation: one warp per node ----------------
__global__ void aggregate_kernel(const float* __restrict__ in_ext, int in_sel, int out_sel) {
    const float* in = in_ext ? in_ext : selbuf(in_sel);
    float* out = selbuf(out_sel);
    int gtid = blockIdx.x * blockDim.x + threadIdx.x;
    int node = gtid >> 5;
    int lane = gtid & 31;
    if (node >= N_NODES) return;
    int beg = g_rowptr[node], end = g_rowptr[node + 1];
    float4 acc0 = make_float4(0.f, 0.f, 0.f, 0.f);
    float4 acc1 = make_float4(0.f, 0.f, 0.f, 0.f);
    for (int p = beg; p < end; p++) {
        int s = g_srcs[p];
        const float4* ps = (const float4*)(in + (size_t)s * D);
        float4 a = ps[lane];
        float4 b = ps[lane + 32];
        acc0.x += a.x; acc0.y += a.y; acc0.z += a.z; acc0.w += a.w;
        acc1.x += b.x; acc1.y += b.y; acc1.z += b.z; acc1.w += b.w;
    }
    float inv = 1.f / fmaxf((float)(end - beg), 1.f);
    acc0.x *= inv; acc0.y *= inv; acc0.z *= inv; acc0.w *= inv;
    acc1.x *= inv; acc1.y *= inv; acc1.z *= inv; acc1.w *= inv;
    float4* po = (float4*)(out + (size_t)node * D);
    po[lane] = acc0;
    po[lane + 32] = acc1;
}

// ---------------- tf32 tensor-core GEMM ----------------
// C[M,256] = act(A1@W1 (+ A2@W2) (+ bias)), K = 256, all row-major, stride 256.
// 128x128 block tile, BK=16 double-buffered, 8 warps of 32x64 (2x8 m16n8k8).
// Smem holds PRE-CONVERTED tf32 bits; inner loop is pure LDS + MMA.
#define BM 128
#define BN 128
#define BK 16

__device__ __forceinline__ uint32_t f2tf32(float f) {
    uint32_t r;
    asm("cvt.rna.tf32.f32 %0, %1;" : "=r"(r) : "f"(f));
    return r;
}

__device__ __forceinline__ uint4 cvt4(float4 v) {
    uint4 r;
    r.x = f2tf32(v.x); r.y = f2tf32(v.y); r.z = f2tf32(v.z); r.w = f2tf32(v.w);
    return r;
}

__device__ __forceinline__ void mma_tf32(float* c, uint32_t a0, uint32_t a1,
                                         uint32_t a2, uint32_t a3,
                                         uint32_t b0, uint32_t b1) {
    asm volatile(
        "mma.sync.aligned.m16n8k8.row.col.f32.tf32.tf32.f32 "
        "{%0,%1,%2,%3}, {%4,%5,%6,%7}, {%8,%9}, {%0,%1,%2,%3};"
        : "+f"(c[0]), "+f"(c[1]), "+f"(c[2]), "+f"(c[3])
        : "r"(a0), "r"(a1), "r"(a2), "r"(a3), "r"(b0), "r"(b1));
}

template <bool DUAL, bool RELU, bool BIAS>
__global__ __launch_bounds__(256, 2)
void gemm_kernel(const float* __restrict__ A1ext, int a1_sel,
                 const float* __restrict__ W1,
                 const float* __restrict__ A2ext, int a2_sel,
                 const float* __restrict__ W2,
                 const float* __restrict__ bias, int c_sel) {
    __shared__ uint32_t As[2][BM][BK + 4];    // stride 20: conflict-free frag reads
    __shared__ uint32_t Ws[2][BK][BN + 8];    // stride 136: conflict-free frag reads

    const float* A1 = A1ext ? A1ext : selbuf(a1_sel);
    const float* A2 = DUAL ? (A2ext ? A2ext : selbuf(a2_sel)) : nullptr;
    float* C = selbuf(c_sel);

    const int tid = threadIdx.x;
    const int lane = tid & 31;
    const int warp = tid >> 5;
    const int wm = warp & 3;          // 4 warps along M
    const int wn = warp >> 2;         // 2 warps along N
    const int m0 = blockIdx.y * BM;
    const int n0 = blockIdx.x * BN;

    const int itersPerPass = 256 / BK;            // 16
    const int total = DUAL ? 2 * itersPerPass : itersPerPass;

    float acc[2][8][4];
#pragma unroll
    for (int i = 0; i < 2; i++)
#pragma unroll
        for (int j = 0; j < 8; j++)
#pragma unroll
            for (int r = 0; r < 4; r++) acc[i][j][r] = 0.f;

    // per-thread load coordinates
    // A tile: 128 rows x 16 k = 512 float4; thread does j = tid, tid+256
    const int ar0 = tid >> 2, ac0 = (tid & 3) * 4;           // j = tid
    const int ar1 = (tid + 256) >> 2;                        // j = tid+256 (same ac)
    // W tile: 16 k x 128 n = 512 float4
    const int wk0 = tid >> 5, wc0 = (tid & 31) * 4;
    const int wk1 = (tid + 256) >> 5;

    auto loadA = [&](const float* A, int kk, float4& v0, float4& v1) {
        int gm0 = m0 + ar0, gm1 = m0 + ar1;
        v0 = (gm0 < N_NODES) ? *(const float4*)(A + (size_t)gm0 * 256 + kk + ac0)
                             : make_float4(0.f, 0.f, 0.f, 0.f);
        v1 = (gm1 < N_NODES) ? *(const float4*)(A + (size_t)gm1 * 256 + kk + ac0)
                             : make_float4(0.f, 0.f, 0.f, 0.f);
    };
    auto loadW = [&](const float* W, int kk, float4& v0, float4& v1) {
        v0 = *(const float4*)(W + (size_t)(kk + wk0) * 256 + n0 + wc0);
        v1 = *(const float4*)(W + (size_t)(kk + wk1) * 256 + n0 + wc0);
    };
    auto storeTile = [&](int buf, const float4& a0v, const float4& a1v,
                         const float4& w0v, const float4& w1v) {
        *(uint4*)&As[buf][ar0][ac0] = cvt4(a0v);
        *(uint4*)&As[buf][ar1][ac0] = cvt4(a1v);
        *(uint4*)&Ws[buf][wk0][wc0] = cvt4(w0v);
        *(uint4*)&Ws[buf][wk1][wc0] = cvt4(w1v);
    };

    // prologue: iter 0 into buffer 0
    {
        float4 a0v, a1v, w0v, w1v;
        loadA(A1, 0, a0v, a1v);
        loadW(W1, 0, w0v, w1v);
        storeTile(0, a0v, a1v, w0v, w1v);
    }
    __syncthreads();

    const int mbase = wm * 32;
    const int nbase = wn * 64;
    const int fr = lane >> 2;      // fragment row
    const int fc = lane & 3;       // fragment col/k

    for (int it = 0; it < total; it++) {
        int buf = it & 1;
        float4 pa0, pa1, pw0, pw1;
        bool more = (it + 1) < total;
        if (more) {
            int nit = it + 1;
            const float* A = (DUAL && nit >= itersPerPass) ? A2 : A1;
            const float* W = (DUAL && nit >= itersPerPass) ? W2 : W1;
            int kk = (nit & (itersPerPass - 1)) * BK;
            loadA(A, kk, pa0, pa1);
            loadW(W, kk, pw0, pw1);
        }

#pragma unroll
        for (int ks = 0; ks < 2; ks++) {
            int kk = ks * 8;
            uint32_t af[2][4];
#pragma unroll
            for (int mt = 0; mt < 2; mt++) {
                int r = mbase + mt * 16 + fr;
                af[mt][0] = As[buf][r][kk + fc];
                af[mt][1] = As[buf][r + 8][kk + fc];
                af[mt][2] = As[buf][r][kk + fc + 4];
                af[mt][3] = As[buf][r + 8][kk + fc + 4];
            }
            uint32_t bf[8][2];
#pragma unroll
            for (int nt = 0; nt < 8; nt++) {
                int n = nbase + nt * 8 + fr;
                bf[nt][0] = Ws[buf][kk + fc][n];
                bf[nt][1] = Ws[buf][kk + fc + 4][n];
            }
#pragma unroll
            for (int mt = 0; mt < 2; mt++)
#pragma unroll
                for (int nt = 0; nt < 8; nt++)
                    mma_tf32(acc[mt][nt], af[mt][0], af[mt][1], af[mt][2], af[mt][3],
                             bf[nt][0], bf[nt][1]);
        }

        if (more) storeTile(buf ^ 1, pa0, pa1, pw0, pw1);
        __syncthreads();
    }

    // epilogue: c0/c1 at (fr, 2*fc), c2/c3 at (fr+8, 2*fc)
#pragma unroll
    for (int mt = 0; mt < 2; mt++) {
#pragma unroll
        for (int nt = 0; nt < 8; nt++) {
            int gn = n0 + nbase + nt * 8 + 2 * fc;
            float b0 = BIAS ? bias[gn] : 0.f;
            float b1 = BIAS ? bias[gn + 1] : 0.f;
            int gm0 = m0 + mbase + mt * 16 + fr;
            int gm1 = gm0 + 8;
            float2 v0, v1;
            v0.x = acc[mt][nt][0] + b0; v0.y = acc[mt][nt][1] + b1;
            v1.x = acc[mt][nt][2] + b0; v1.y = acc[mt][nt][3] + b1;
            if (RELU) {
                v0.x = fmaxf(v0.x, 0.f); v0.y = fmaxf(v0.y, 0.f);
                v1.x = fmaxf(v1.x, 0.f); v1.y = fmaxf(v1.y, 0.f);
            }
            if (gm0 < N_NODES) *(float2*)(C + (size_t)gm0 * 256 + gn) = v0;
            if (gm1 < N_NODES) *(float2*)(C + (size_t)gm1 * 256 + gn) = v1;
        }
    }
}

// ---------------- edge MLP: one warp per edge ----------------
__global__ void edge_kernel(const float* __restrict__ Wm2,
                            const float* __restrict__ bm2,
                            float* __restrict__ out) {
    __shared__ __align__(16) float w0[256];
    __shared__ __align__(16) float w1[256];
    for (int i = threadIdx.x; i < 256; i += blockDim.x) {
        w0[i] = Wm2[i * 2 + 0];
        w1[i] = Wm2[i * 2 + 1];
    }
    __syncthreads();

    int gtid = blockIdx.x * blockDim.x + threadIdx.x;
    int e = gtid >> 5;
    int lane = gtid & 31;
    if (e >= N_EDGES) return;

    int s = g_esrc[e];
    int d = g_edst[e];
    const float4* pa = (const float4*)(g_bufA + (size_t)s * D);
    const float4* pb = (const float4*)(g_bufB + (size_t)d * D);
    const float4* w0f = (const float4*)w0;
    const float4* w1f = (const float4*)w1;

    float acc0 = 0.f, acc1 = 0.f;
#pragma unroll
    for (int i = 0; i < 2; i++) {
        int idx = lane + i * 32;
        float4 a = pa[idx];
        float4 b = pb[idx];
        float4 v;
        v.x = fmaxf(a.x + b.x, 0.f);
        v.y = fmaxf(a.y + b.y, 0.f);
        v.z = fmaxf(a.z + b.z, 0.f);
        v.w = fmaxf(a.w + b.w, 0.f);
        float4 wa = w0f[idx];
        float4 wb = w1f[idx];
        acc0 = fmaf(v.x, wa.x, acc0); acc0 = fmaf(v.y, wa.y, acc0);
        acc0 = fmaf(v.z, wa.z, acc0); acc0 = fmaf(v.w, wa.w, acc0);
        acc1 = fmaf(v.x, wb.x, acc1); acc1 = fmaf(v.y, wb.y, acc1);
        acc1 = fmaf(v.z, wb.z, acc1); acc1 = fmaf(v.w, wb.w, acc1);
    }
#pragma unroll
    for (int o = 16; o > 0; o >>= 1) {
        acc0 += __shfl_xor_sync(0xFFFFFFFFu, acc0, o);
        acc1 += __shfl_xor_sync(0xFFFFFFFFu, acc1, o);
    }
    if (lane == 0) {
        float2 r;
        r.x = acc0 + bm2[0];
        r.y = acc1 + bm2[1];
        *(float2*)(out + (size_t)e * 2) = r;
    }
}

// ---------------- launch ----------------
extern "C" void kernel_launch(void* const* d_in, const int* in_sizes, int n_in,
                              void* d_out, int out_size) {
    const float* x   = (const float*)d_in[0];
    const void*  ei  = d_in[1];
    const float* W1l = (const float*)d_in[2];
    const float* b1l = (const float*)d_in[3];
    const float* W1r = (const float*)d_in[4];
    const float* W2l = (const float*)d_in[5];
    const float* b2l = (const float*)d_in[6];
    const float* W2r = (const float*)d_in[7];
    const float* Wm1 = (const float*)d_in[8];
    const float* bm1 = (const float*)d_in[9];
    const float* Wm2 = (const float*)d_in[10];
    const float* bm2 = (const float*)d_in[11];
    float* out = (float*)d_out;

    // edge-index ingestion (robust to int32 vs int64 delivery)
    detect_kernel<<<1, 32>>>((const int*)ei);
    convert_kernel<<<(N_EDGES + 255) / 256, 256>>>(ei);

    // CSR build
    zero_deg_kernel<<<(N_NODES + 255) / 256, 256>>>();
    count_kernel<<<(N_EDGES + 255) / 256, 256>>>();
    scan_kernel<<<1, 1024>>>();
    fill_kernel<<<(N_EDGES + 255) / 256, 256>>>();

    dim3 ggrid(2, (N_NODES + BM - 1) / BM);
    int aggBlocks = (N_NODES * 32 + 255) / 256;
    int edgeBlocks = (N_EDGES * 32 + 255) / 256;

    // layer 1: agg(x) -> bufA(0) ; h1 = relu(agg@W1l + x@W1r + b1l) -> bufB(1)
    aggregate_kernel<<<aggBlocks, 256>>>(x, -1, 0);
    gemm_kernel<true, true, true><<<ggrid, 256>>>(nullptr, 0, W1l, x, -1, W1r, b1l, 1);

    // layer 2: agg(h1) -> bufA(0) ; h2 = relu(agg@W2l + h1@W2r + b2l) -> bufC(2)
    aggregate_kernel<<<aggBlocks, 256>>>(nullptr, 1, 0);
    gemm_kernel<true, true, true><<<ggrid, 256>>>(nullptr, 0, W2l, nullptr, 1, W2r, b2l, 2);

    // edge precompute: A_pre = h2 @ Wm1_top -> bufA(0) ; B_pre = h2 @ Wm1_bot + bm1 -> bufB(1)
    gemm_kernel<false, false, false><<<ggrid, 256>>>(nullptr, 2, Wm1, nullptr, -1, nullptr, nullptr, 0);
    gemm_kernel<false, false, true><<<ggrid, 256>>>(nullptr, 2, Wm1 + 256 * 256, nullptr, -1, nullptr, bm1, 1);

    // edge MLP
    edge_kernel<<<edgeBlocks, 256>>>(Wm2, bm2, out);
}

// round 9
// speedup vs baseline: 1.8943x; 1.1055x over previous
#include <cuda_runtime.h>
#include <cstdint>

#define N_NODES 50000
#define N_EDGES 800000
#define D 256

// ---------------- scratch (device globals; no allocations) ----------------
__device__ int   g_is64;
__device__ int   g_esrc[N_EDGES];
__device__ int   g_edst[N_EDGES];
__device__ int   g_deg[N_NODES];
__device__ int   g_rowptr[N_NODES + 1];
__device__ int   g_cursor[N_NODES];
__device__ int   g_srcs[N_EDGES];
__device__ int   g_eid[N_EDGES];
__device__ float g_bufA[N_NODES * D];   // agg scratch, later A_pre
__device__ float g_bufB[N_NODES * D];   // h1, later B_pre
__device__ float g_bufC[N_NODES * D];   // h2

// selector: 0 -> g_bufA, 1 -> g_bufB, 2 -> g_bufC, else nullptr
__device__ __forceinline__ float* selbuf(int s) {
    if (s == 0) return g_bufA;
    if (s == 1) return g_bufB;
    if (s == 2) return g_bufC;
    return nullptr;
}

// ---------------- detect dtype + zero degrees (fused) ----------------
__global__ void detect_zero_kernel(const int* __restrict__ ei32) {
    int i = blockIdx.x * blockDim.x + threadIdx.x;
    if (i < N_NODES) g_deg[i] = 0;
    if (i == 0) {
        int allzero = 1;
        for (int j = 1; j < 256; j += 2) {
            if (ei32[j] != 0) { allzero = 0; break; }
        }
        g_is64 = allzero;
    }
}

// ---------------- convert edge index + count degrees (fused) ----------------
__global__ void convert_count_kernel(const void* __restrict__ ei) {
    int e = blockIdx.x * blockDim.x + threadIdx.x;
    if (e >= N_EDGES) return;
    int s, d;
    if (g_is64) {
        const long long* p = (const long long*)ei;
        s = (int)p[e];
        d = (int)p[N_EDGES + e];
    } else {
        const int* p = (const int*)ei;
        s = p[e];
        d = p[N_EDGES + e];
    }
    g_esrc[e] = s;
    g_edst[e] = d;
    atomicAdd(&g_deg[d], 1);
}

__global__ void scan_kernel() {
    __shared__ int sh[1024];
    const int CH = 49;
    int t = threadIdx.x;
    int base = t * CH;
    int s = 0;
    for (int i = 0; i < CH; i++) {
        int idx = base + i;
        if (idx < N_NODES) s += g_deg[idx];
    }
    sh[t] = s;
    __syncthreads();
    for (int o = 1; o < 1024; o <<= 1) {
        int v = (t >= o) ? sh[t - o] : 0;
        __syncthreads();
        sh[t] += v;
        __syncthreads();
    }
    int run = sh[t] - s;
    for (int i = 0; i < CH; i++) {
        int idx = base + i;
        if (idx < N_NODES) {
            g_rowptr[idx] = run;
            g_cursor[idx] = run;
            run += g_deg[idx];
        }
    }
    if (t == 0) g_rowptr[N_NODES] = N_EDGES;
}

__global__ void fill_kernel() {
    int e = blockIdx.x * blockDim.x + threadIdx.x;
    if (e < N_EDGES) {
        int pos = atomicAdd(&g_cursor[g_edst[e]], 1);
        g_srcs[pos] = g_esrc[e];
        g_eid[pos] = e;
    }
}

// ---------------- mean aggregation: one warp per node ----------------
__global__ void aggregate_kernel(const float* __restrict__ in_ext, int in_sel, int out_sel) {
    const float* in = in_ext ? in_ext : selbuf(in_sel);
    float* out = selbuf(out_sel);
    int gtid = blockIdx.x * blockDim.x + threadIdx.x;
    int node = gtid >> 5;
    int lane = gtid & 31;
    if (node >= N_NODES) return;
    int beg = g_rowptr[node], end = g_rowptr[node + 1];
    float4 acc0 = make_float4(0.f, 0.f, 0.f, 0.f);
    float4 acc1 = make_float4(0.f, 0.f, 0.f, 0.f);
    for (int p = beg; p < end; p++) {
        int s = g_srcs[p];
        const float4* ps = (const float4*)(in + (size_t)s * D);
        float4 a = ps[lane];
        float4 b = ps[lane + 32];
        acc0.x += a.x; acc0.y += a.y; acc0.z += a.z; acc0.w += a.w;
        acc1.x += b.x; acc1.y += b.y; acc1.z += b.z; acc1.w += b.w;
    }
    float inv = 1.f / fmaxf((float)(end - beg), 1.f);
    acc0.x *= inv; acc0.y *= inv; acc0.z *= inv; acc0.w *= inv;
    acc1.x *= inv; acc1.y *= inv; acc1.z *= inv; acc1.w *= inv;
    float4* po = (float4*)(out + (size_t)node * D);
    po[lane] = acc0;
    po[lane + 32] = acc1;
}

// ---------------- tf32 tensor-core GEMM ----------------
// C[M,256] = act(A1@W1 (+ A2@W2) (+ bias)), K = 256, all row-major, stride 256.
// 128x128 block tile, BK=16 double-buffered, 8 warps of 32x64 (2x8 m16n8k8).
// Smem holds PRE-CONVERTED tf32 bits; inner loop is pure LDS + MMA.
#define BM 128
#define BN 128
#define BK 16

__device__ __forceinline__ uint32_t f2tf32(float f) {
    uint32_t r;
    asm("cvt.rna.tf32.f32 %0, %1;" : "=r"(r) : "f"(f));
    return r;
}

__device__ __forceinline__ uint4 cvt4(float4 v) {
    uint4 r;
    r.x = f2tf32(v.x); r.y = f2tf32(v.y); r.z = f2tf32(v.z); r.w = f2tf32(v.w);
    return r;
}

__device__ __forceinline__ void mma_tf32(float* c, uint32_t a0, uint32_t a1,
                                         uint32_t a2, uint32_t a3,
                                         uint32_t b0, uint32_t b1) {
    asm volatile(
        "mma.sync.aligned.m16n8k8.row.col.f32.tf32.tf32.f32 "
        "{%0,%1,%2,%3}, {%4,%5,%6,%7}, {%8,%9}, {%0,%1,%2,%3};"
        : "+f"(c[0]), "+f"(c[1]), "+f"(c[2]), "+f"(c[3])
        : "r"(a0), "r"(a1), "r"(a2), "r"(a3), "r"(b0), "r"(b1));
}

template <bool DUAL, bool RELU, bool BIAS>
__global__ __launch_bounds__(256, 2)
void gemm_kernel(const float* __restrict__ A1ext, int a1_sel,
                 const float* __restrict__ W1,
                 const float* __restrict__ A2ext, int a2_sel,
                 const float* __restrict__ W2,
                 const float* __restrict__ bias, int c_sel) {
    __shared__ uint32_t As[2][BM][BK + 4];    // stride 20: conflict-free frag reads
    __shared__ uint32_t Ws[2][BK][BN + 8];    // stride 136: conflict-free frag reads

    const float* A1 = A1ext ? A1ext : selbuf(a1_sel);
    const float* A2 = DUAL ? (A2ext ? A2ext : selbuf(a2_sel)) : nullptr;
    float* C = selbuf(c_sel);

    const int tid = threadIdx.x;
    const int lane = tid & 31;
    const int warp = tid >> 5;
    const int wm = warp & 3;          // 4 warps along M
    const int wn = warp >> 2;         // 2 warps along N
    const int m0 = blockIdx.y * BM;
    const int n0 = blockIdx.x * BN;

    const int itersPerPass = 256 / BK;            // 16
    const int total = DUAL ? 2 * itersPerPass : itersPerPass;

    float acc[2][8][4];
#pragma unroll
    for (int i = 0; i < 2; i++)
#pragma unroll
        for (int j = 0; j < 8; j++)
#pragma unroll
            for (int r = 0; r < 4; r++) acc[i][j][r] = 0.f;

    // per-thread load coordinates
    const int ar0 = tid >> 2, ac0 = (tid & 3) * 4;
    const int ar1 = (tid + 256) >> 2;
    const int wk0 = tid >> 5, wc0 = (tid & 31) * 4;
    const int wk1 = (tid + 256) >> 5;

    auto loadA = [&](const float* A, int kk, float4& v0, float4& v1) {
        int gm0 = m0 + ar0, gm1 = m0 + ar1;
        v0 = (gm0 < N_NODES) ? *(const float4*)(A + (size_t)gm0 * 256 + kk + ac0)
                             : make_float4(0.f, 0.f, 0.f, 0.f);
        v1 = (gm1 < N_NODES) ? *(const float4*)(A + (size_t)gm1 * 256 + kk + ac0)
                             : make_float4(0.f, 0.f, 0.f, 0.f);
    };
    auto loadW = [&](const float* W, int kk, float4& v0, float4& v1) {
        v0 = *(const float4*)(W + (size_t)(kk + wk0) * 256 + n0 + wc0);
        v1 = *(const float4*)(W + (size_t)(kk + wk1) * 256 + n0 + wc0);
    };
    auto storeTile = [&](int buf, const float4& a0v, const float4& a1v,
                         const float4& w0v, const float4& w1v) {
        *(uint4*)&As[buf][ar0][ac0] = cvt4(a0v);
        *(uint4*)&As[buf][ar1][ac0] = cvt4(a1v);
        *(uint4*)&Ws[buf][wk0][wc0] = cvt4(w0v);
        *(uint4*)&Ws[buf][wk1][wc0] = cvt4(w1v);
    };

    // prologue: iter 0 into buffer 0
    {
        float4 a0v, a1v, w0v, w1v;
        loadA(A1, 0, a0v, a1v);
        loadW(W1, 0, w0v, w1v);
        storeTile(0, a0v, a1v, w0v, w1v);
    }
    __syncthreads();

    const int mbase = wm * 32;
    const int nbase = wn * 64;
    const int fr = lane >> 2;      // fragment row
    const int fc = lane & 3;       // fragment col/k

    for (int it = 0; it < total; it++) {
        int buf = it & 1;
        float4 pa0, pa1, pw0, pw1;
        bool more = (it + 1) < total;
        if (more) {
            int nit = it + 1;
            const float* A = (DUAL && nit >= itersPerPass) ? A2 : A1;
            const float* W = (DUAL && nit >= itersPerPass) ? W2 : W1;
            int kk = (nit & (itersPerPass - 1)) * BK;
            loadA(A, kk, pa0, pa1);
            loadW(W, kk, pw0, pw1);
        }

#pragma unroll
        for (int ks = 0; ks < 2; ks++) {
            int kk = ks * 8;
            uint32_t af[2][4];
#pragma unroll
            for (int mt = 0; mt < 2; mt++) {
                int r = mbase + mt * 16 + fr;
                af[mt][0] = As[buf][r][kk + fc];
                af[mt][1] = As[buf][r + 8][kk + fc];
                af[mt][2] = As[buf][r][kk + fc + 4];
                af[mt][3] = As[buf][r + 8][kk + fc + 4];
            }
            uint32_t bf[8][2];
#pragma unroll
            for (int nt = 0; nt < 8; nt++) {
                int n = nbase + nt * 8 + fr;
                bf[nt][0] = Ws[buf][kk + fc][n];
                bf[nt][1] = Ws[buf][kk + fc + 4][n];
            }
#pragma unroll
            for (int mt = 0; mt < 2; mt++)
#pragma unroll
                for (int nt = 0; nt < 8; nt++)
                    mma_tf32(acc[mt][nt], af[mt][0], af[mt][1], af[mt][2], af[mt][3],
                             bf[nt][0], bf[nt][1]);
        }

        if (more) storeTile(buf ^ 1, pa0, pa1, pw0, pw1);
        __syncthreads();
    }

    // epilogue: c0/c1 at (fr, 2*fc), c2/c3 at (fr+8, 2*fc)
#pragma unroll
    for (int mt = 0; mt < 2; mt++) {
#pragma unroll
        for (int nt = 0; nt < 8; nt++) {
            int gn = n0 + nbase + nt * 8 + 2 * fc;
            float b0 = BIAS ? bias[gn] : 0.f;
            float b1 = BIAS ? bias[gn + 1] : 0.f;
            int gm0 = m0 + mbase + mt * 16 + fr;
            int gm1 = gm0 + 8;
            float2 v0, v1;
            v0.x = acc[mt][nt][0] + b0; v0.y = acc[mt][nt][1] + b1;
            v1.x = acc[mt][nt][2] + b0; v1.y = acc[mt][nt][3] + b1;
            if (RELU) {
                v0.x = fmaxf(v0.x, 0.f); v0.y = fmaxf(v0.y, 0.f);
                v1.x = fmaxf(v1.x, 0.f); v1.y = fmaxf(v1.y, 0.f);
            }
            if (gm0 < N_NODES) *(float2*)(C + (size_t)gm0 * 256 + gn) = v0;
            if (gm1 < N_NODES) *(float2*)(C + (size_t)gm1 * 256 + gn) = v1;
        }
    }
}

// ---------------- edge MLP, CSR order: one warp per DST node ----------------
// out[eid] = relu(A_pre[src] + B_pre[dst]) @ [w0,w1] + bm2
// B_pre[dst] row is loaded once per node into registers and reused across its edges.
__global__ void edge_kernel_csr(const float* __restrict__ Wm2,
                                const float* __restrict__ bm2,
                                float* __restrict__ out) {
    __shared__ __align__(16) float w0[256];
    __shared__ __align__(16) float w1[256];
    for (int i = threadIdx.x; i < 256; i += blockDim.x) {
        w0[i] = Wm2[i * 2 + 0];
        w1[i] = Wm2[i * 2 + 1];
    }
    __syncthreads();

    int gtid = blockIdx.x * blockDim.x + threadIdx.x;
    int node = gtid >> 5;
    int lane = gtid & 31;
    if (node >= N_NODES) return;

    int beg = g_rowptr[node], end = g_rowptr[node + 1];
    if (beg == end) return;

    // load B_pre[node] row once (8 floats per lane)
    const float4* pb = (const float4*)(g_bufB + (size_t)node * D);
    float4 b0 = pb[lane];
    float4 b1 = pb[lane + 32];

    // weight segments for this lane
    const float4* w0f = (const float4*)w0;
    const float4* w1f = (const float4*)w1;
    float4 wa0 = w0f[lane], wa1 = w0f[lane + 32];
    float4 wb0 = w1f[lane], wb1 = w1f[lane + 32];

    float bias0 = bm2[0], bias1 = bm2[1];

    for (int p = beg; p < end; p++) {
        int s = g_srcs[p];
        int eid = g_eid[p];
        const float4* pa = (const float4*)(g_bufA + (size_t)s * D);
        float4 a0 = pa[lane];
        float4 a1 = pa[lane + 32];

        float4 v0, v1;
        v0.x = fmaxf(a0.x + b0.x, 0.f); v0.y = fmaxf(a0.y + b0.y, 0.f);
        v0.z = fmaxf(a0.z + b0.z, 0.f); v0.w = fmaxf(a0.w + b0.w, 0.f);
        v1.x = fmaxf(a1.x + b1.x, 0.f); v1.y = fmaxf(a1.y + b1.y, 0.f);
        v1.z = fmaxf(a1.z + b1.z, 0.f); v1.w = fmaxf(a1.w + b1.w, 0.f);

        float acc0 = 0.f, acc1 = 0.f;
        acc0 = fmaf(v0.x, wa0.x, acc0); acc0 = fmaf(v0.y, wa0.y, acc0);
        acc0 = fmaf(v0.z, wa0.z, acc0); acc0 = fmaf(v0.w, wa0.w, acc0);
        acc0 = fmaf(v1.x, wa1.x, acc0); acc0 = fmaf(v1.y, wa1.y, acc0);
        acc0 = fmaf(v1.z, wa1.z, acc0); acc0 = fmaf(v1.w, wa1.w, acc0);
        acc1 = fmaf(v0.x, wb0.x, acc1); acc1 = fmaf(v0.y, wb0.y, acc1);
        acc1 = fmaf(v0.z, wb0.z, acc1); acc1 = fmaf(v0.w, wb0.w, acc1);
        acc1 = fmaf(v1.x, wb1.x, acc1); acc1 = fmaf(v1.y, wb1.y, acc1);
        acc1 = fmaf(v1.z, wb1.z, acc1); acc1 = fmaf(v1.w, wb1.w, acc1);

#pragma unroll
        for (int o = 16; o > 0; o >>= 1) {
            acc0 += __shfl_xor_sync(0xFFFFFFFFu, acc0, o);
            acc1 += __shfl_xor_sync(0xFFFFFFFFu, acc1, o);
        }
        if (lane == 0) {
            float2 r;
            r.x = acc0 + bias0;
            r.y = acc1 + bias1;
            *(float2*)(out + (size_t)eid * 2) = r;
        }
    }
}

// ---------------- launch ----------------
extern "C" void kernel_launch(void* const* d_in, const int* in_sizes, int n_in,
                              void* d_out, int out_size) {
    const float* x   = (const float*)d_in[0];
    const void*  ei  = d_in[1];
    const float* W1l = (const float*)d_in[2];
    const float* b1l = (const float*)d_in[3];
    const float* W1r = (const float*)d_in[4];
    const float* W2l = (const float*)d_in[5];
    const float* b2l = (const float*)d_in[6];
    const float* W2r = (const float*)d_in[7];
    const float* Wm1 = (const float*)d_in[8];
    const float* bm1 = (const float*)d_in[9];
    const float* Wm2 = (const float*)d_in[10];
    const float* bm2 = (const float*)d_in[11];
    float* out = (float*)d_out;

    // detect dtype + zero degrees; convert + count (fused passes)
    detect_zero_kernel<<<(N_NODES + 255) / 256, 256>>>((const int*)ei);
    convert_count_kernel<<<(N_EDGES + 255) / 256, 256>>>(ei);
    scan_kernel<<<1, 1024>>>();
    fill_kernel<<<(N_EDGES + 255) / 256, 256>>>();

    dim3 ggrid(2, (N_NODES + BM - 1) / BM);
    int aggBlocks = (N_NODES * 32 + 255) / 256;
    int nodeWarpBlocks = (N_NODES * 32 + 255) / 256;

    // layer 1: agg(x) -> bufA(0) ; h1 = relu(agg@W1l + x@W1r + b1l) -> bufB(1)
    aggregate_kernel<<<aggBlocks, 256>>>(x, -1, 0);
    gemm_kernel<true, true, true><<<ggrid, 256>>>(nullptr, 0, W1l, x, -1, W1r, b1l, 1);

    // layer 2: agg(h1) -> bufA(0) ; h2 = relu(agg@W2l + h1@W2r + b2l) -> bufC(2)
    aggregate_kernel<<<aggBlocks, 256>>>(nullptr, 1, 0);
    gemm_kernel<true, true, true><<<ggrid, 256>>>(nullptr, 0, W2l, nullptr, 1, W2r, b2l, 2);

    // edge precompute: A_pre = h2 @ Wm1_top -> bufA(0) ; B_pre = h2 @ Wm1_bot + bm1 -> bufB(1)
    gemm_kernel<false, false, false><<<ggrid, 256>>>(nullptr, 2, Wm1, nullptr, -1, nullptr, nullptr, 0);
    gemm_kernel<false, false, true><<<ggrid, 256>>>(nullptr, 2, Wm1 + 256 * 256, nullptr, -1, nullptr, bm1, 1);

    // edge MLP in CSR (dst-grouped) order
    edge_kernel_csr<<<nodeWarpBlocks, 256>>>(Wm2, bm2, out);
}